// round 5
// baseline (speedup 1.0000x reference)
#include <cuda_runtime.h>
#include <cuda_bf16.h>
#include <math.h>

// ---------------- problem constants ----------------
#define D_MODEL   768
#define D_STATE   64
#define D_CONV    4
#define HEADDIM   64
#define D_INNER   1536
#define NHEADS    24
#define CONV_DIM  1664          // D_INNER + 2*D_STATE
#define D_IN_PROJ 3224          // 2*D_INNER + 2*D_STATE + NHEADS
#define BSZ       2
#define SEQ       512
#define NTOK      (BSZ*SEQ)     // 1024
#define EPS       1e-5f
#define D_FF      3072

// ---------------- scratch (device globals; no allocation allowed) ------------
__device__ float g_xn   [NTOK * D_MODEL];          // LN1 output
__device__ float g_zx   [NTOK * D_IN_PROJ];        // in_proj output
__device__ float g_dt   [NTOK * NHEADS];           // softplus(dt + bias)
__device__ float g_dA   [NTOK * NHEADS];           // exp(-exp(A_log)*dt)
__device__ float g_conv [2 * NTOK * CONV_DIM];     // conv+silu, per direction
__device__ float g_y    [2 * NTOK * D_INNER];      // scan output (orig coords)
__device__ float g_ysum [NTOK * D_INNER];          // gated+normed fwd+bwd
__device__ float g_mp   [NTOK * D_MODEL];          // out_f + out_b
__device__ float g_m    [NTOK * D_MODEL];          // LN2 output
__device__ float g_ff1  [NTOK * D_FF];             // gelu(m@W1+b1)

// ---------------- small device helpers ----------------
__device__ __forceinline__ float sigmoidf_(float x) { return 1.0f / (1.0f + __expf(-x)); }
__device__ __forceinline__ float siluf_(float x)    { return x * sigmoidf_(x); }
__device__ __forceinline__ float softplusf_(float x){ return (x > 20.0f) ? x : log1pf(expf(x)); }
__device__ __forceinline__ float geluf_(float x)    { return 0.5f * x * (1.0f + erff(x * 0.70710678118654752f)); }

// block reduction over 256 threads (sum)
__device__ __forceinline__ float block_sum_256(float v, float* sh) {
    #pragma unroll
    for (int o = 16; o; o >>= 1) v += __shfl_xor_sync(0xffffffffu, v, o);
    if ((threadIdx.x & 31) == 0) sh[threadIdx.x >> 5] = v;
    __syncthreads();
    float s = (threadIdx.x < 8) ? sh[threadIdx.x] : 0.0f;
    if (threadIdx.x < 8) {
        #pragma unroll
        for (int o = 4; o; o >>= 1) s += __shfl_xor_sync(0xffu, s, o);
        if (threadIdx.x == 0) sh[0] = s;
    }
    __syncthreads();
    float r = sh[0];
    __syncthreads();
    return r;
}

// ---------------- layernorm: 1 block / token, 256 threads, D=768 -------------
__global__ __launch_bounds__(256) void ln_kernel(
    const float* __restrict__ x, const float* __restrict__ w,
    const float* __restrict__ b, float* __restrict__ out)
{
    __shared__ float sh[8];
    const int tok = blockIdx.x;
    const float* xi = x + (size_t)tok * D_MODEL;
    float v[3];
    #pragma unroll
    for (int i = 0; i < 3; i++) v[i] = xi[threadIdx.x + i * 256];
    float s = v[0] + v[1] + v[2];
    s = block_sum_256(s, sh);
    const float mu = s * (1.0f / D_MODEL);
    float c[3], sq = 0.0f;
    #pragma unroll
    for (int i = 0; i < 3; i++) { c[i] = v[i] - mu; sq += c[i] * c[i]; }
    sq = block_sum_256(sq, sh);
    const float rstd = rsqrtf(sq * (1.0f / D_MODEL) + EPS);
    float* yo = out + (size_t)tok * D_MODEL;
    #pragma unroll
    for (int i = 0; i < 3; i++) {
        int idx = threadIdx.x + i * 256;
        yo[idx] = c[i] * rstd * w[idx] + b[idx];
    }
}

// ---------------- dt preprocessing ----------------
__global__ __launch_bounds__(256) void dt_kernel(
    const float* __restrict__ zx, const float* __restrict__ dt_bias,
    const float* __restrict__ A_log, float* __restrict__ dt_sp, float* __restrict__ dA)
{
    int idx = blockIdx.x * 256 + threadIdx.x;          // NTOK*NHEADS = 24576
    if (idx >= NTOK * NHEADS) return;
    int h = idx % NHEADS;
    int tok = idx / NHEADS;
    float v = zx[(size_t)tok * D_IN_PROJ + (2 * D_INNER + 2 * D_STATE - D_STATE * 0) - 24 + 24 + 3200 - 3224 + 3200 + h]; // see below
    // simplified: dt columns are [3200, 3224)
    v = zx[(size_t)tok * D_IN_PROJ + 3200 + h];
    float sp = softplusf_(v + dt_bias[h]);
    dt_sp[idx] = sp;
    dA[idx] = __expf(-__expf(A_log[h]) * sp);
}

// ---------------- conv1d (+bias, silu), both directions ----------------
// dir 0 (causal):      acc = w0*X(t-3)+w1*X(t-2)+w2*X(t-1)+w3*X(t)
// dir 1 (anti-causal): acc = w0*X(t+3)+w1*X(t+2)+w2*X(t+1)+w3*X(t)
__global__ __launch_bounds__(256) void conv_kernel(
    const float* __restrict__ zx, const float* __restrict__ conv_w,
    const float* __restrict__ conv_b, float* __restrict__ out)
{
    long long idx = (long long)blockIdx.x * 256 + threadIdx.x;
    const long long total = 2LL * NTOK * CONV_DIM;
    if (idx >= total) return;
    int c = (int)(idx % CONV_DIM);
    long long r = idx / CONV_DIM;
    int t = (int)(r % SEQ);
    r /= SEQ;
    int b = (int)(r % BSZ);
    int dir = (int)(r / BSZ);
    const float4 w = *(const float4*)(conv_w + (size_t)c * 4);
    const float* base = zx + ((size_t)b * SEQ) * D_IN_PROJ + D_INNER + c;
    float acc = 0.0f;
    if (dir == 0) {
        if (t >= 3) acc += w.x * base[(size_t)(t - 3) * D_IN_PROJ];
        if (t >= 2) acc += w.y * base[(size_t)(t - 2) * D_IN_PROJ];
        if (t >= 1) acc += w.z * base[(size_t)(t - 1) * D_IN_PROJ];
        acc += w.w * base[(size_t)t * D_IN_PROJ];
    } else {
        if (t + 3 < SEQ) acc += w.x * base[(size_t)(t + 3) * D_IN_PROJ];
        if (t + 2 < SEQ) acc += w.y * base[(size_t)(t + 2) * D_IN_PROJ];
        if (t + 1 < SEQ) acc += w.z * base[(size_t)(t + 1) * D_IN_PROJ];
        acc += w.w * base[(size_t)t * D_IN_PROJ];
    }
    acc += conv_b[c];
    out[idx] = siluf_(acc);
}

// ---------------- SSM scan: 1 block / (head, batch, dir); 64 threads ---------
// thread p owns h[p, 0..63] in registers.
__global__ __launch_bounds__(64) void scan_kernel(
    const float* __restrict__ conv, const float* __restrict__ dt_sp,
    const float* __restrict__ dA_g, const float* __restrict__ D_param,
    float* __restrict__ y_out)
{
    const int hd  = blockIdx.x;
    const int b   = blockIdx.y;
    const int dir = blockIdx.z;
    const int p   = threadIdx.x;
    const float Dh = D_param[hd];
    float h[64];
    #pragma unroll
    for (int n = 0; n < 64; n++) h[n] = 0.0f;

    __shared__ __align__(16) float Bs[64];
    __shared__ __align__(16) float Cs[64];

    for (int step = 0; step < SEQ; step++) {
        const int s = dir ? (SEQ - 1 - step) : step;
        const float* row = conv + ((size_t)(dir * BSZ + b) * SEQ + s) * CONV_DIM;
        __syncthreads();
        Bs[p] = row[D_INNER + p];
        Cs[p] = row[D_INNER + D_STATE + p];
        __syncthreads();
        const float xp = row[hd * HEADDIM + p];
        const int th = (b * SEQ + s) * NHEADS + hd;
        const float dt = dt_sp[th];
        const float da = dA_g[th];
        const float coeff = dt * xp;
        float acc = 0.0f;
        const float4* B4 = (const float4*)Bs;
        const float4* C4 = (const float4*)Cs;
        #pragma unroll
        for (int n4 = 0; n4 < 16; n4++) {
            float4 bb = B4[n4];
            float4 cc = C4[n4];
            h[4*n4+0] = da * h[4*n4+0] + coeff * bb.x;  acc += h[4*n4+0] * cc.x;
            h[4*n4+1] = da * h[4*n4+1] + coeff * bb.y;  acc += h[4*n4+1] * cc.y;
            h[4*n4+2] = da * h[4*n4+2] + coeff * bb.z;  acc += h[4*n4+2] * cc.z;
            h[4*n4+3] = da * h[4*n4+3] + coeff * bb.w;  acc += h[4*n4+3] * cc.w;
        }
        y_out[((size_t)(dir * BSZ + b) * SEQ + s) * D_INNER + hd * HEADDIM + p] = acc + Dh * xp;
    }
}

// ---------------- gate (silu(z)) + RMSNorm per direction, then sum -----------
__global__ __launch_bounds__(256) void gate_kernel(
    const float* __restrict__ y, const float* __restrict__ zx,
    const float* __restrict__ norm_w, float* __restrict__ ysum)
{
    __shared__ float sh[8];
    const int t = blockIdx.x;
    const int b = blockIdx.y;
    const size_t tok = (size_t)b * SEQ + t;
    const float* zrow = zx + tok * D_IN_PROJ;          // z is [0, D_INNER)
    const float* yf = y + tok * D_INNER;
    const float* yb = y + ((size_t)BSZ * SEQ + tok) * D_INNER;

    float gf[6], gb[6];
    float sf = 0.0f, sb = 0.0f;
    #pragma unroll
    for (int i = 0; i < 6; i++) {
        int c = threadIdx.x + i * 256;
        float g = siluf_(zrow[c]);
        gf[i] = yf[c] * g;  sf += gf[i] * gf[i];
        gb[i] = yb[c] * g;  sb += gb[i] * gb[i];
    }
    sf = block_sum_256(sf, sh);
    sb = block_sum_256(sb, sh);
    const float scf = rsqrtf(sf * (1.0f / D_INNER) + EPS);
    const float scb = rsqrtf(sb * (1.0f / D_INNER) + EPS);
    float* o = ysum + tok * D_INNER;
    #pragma unroll
    for (int i = 0; i < 6; i++) {
        int c = threadIdx.x + i * 256;
        o[c] = (gf[i] * scf + gb[i] * scb) * norm_w[c];
    }
}

// ---------------- GEMM: C[M,N] = A[M,K] @ Bw[N,K]^T, fp32 SIMT --------------
// EPI 0: plain   EPI 1: gelu(x+bias)   EPI 2: x+bias+resid
template<int EPI>
__global__ __launch_bounds__(256) void gemm_kernel(
    const float* __restrict__ A, const float* __restrict__ Bw,
    const float* __restrict__ bias, const float* __restrict__ resid,
    float* __restrict__ C, int M, int N, int K)
{
    __shared__ __align__(16) float As[16][68];
    __shared__ __align__(16) float Bs[16][68];
    const int tid = threadIdx.x;
    const int m0 = blockIdx.y * 64;
    const int n0 = blockIdx.x * 64;
    const int lr = tid >> 2;     // 0..63
    const int lc = tid & 3;      // k-chunk
    const int tx = tid & 15;
    const int ty = tid >> 4;

    float acc[4][4];
    #pragma unroll
    for (int i = 0; i < 4; i++)
        #pragma unroll
        for (int j = 0; j < 4; j++) acc[i][j] = 0.0f;

    for (int k0 = 0; k0 < K; k0 += 16) {
        {
            int row = m0 + lr;
            float4 v = make_float4(0.f, 0.f, 0.f, 0.f);
            if (row < M) v = *(const float4*)(A + (size_t)row * K + k0 + lc * 4);
            As[lc*4+0][lr] = v.x; As[lc*4+1][lr] = v.y;
            As[lc*4+2][lr] = v.z; As[lc*4+3][lr] = v.w;
        }
        {
            int row = n0 + lr;
            float4 v = make_float4(0.f, 0.f, 0.f, 0.f);
            if (row < N) v = *(const float4*)(Bw + (size_t)row * K + k0 + lc * 4);
            Bs[lc*4+0][lr] = v.x; Bs[lc*4+1][lr] = v.y;
            Bs[lc*4+2][lr] = v.z; Bs[lc*4+3][lr] = v.w;
        }
        __syncthreads();
        #pragma unroll
        for (int k = 0; k < 16; k++) {
            float4 a4 = *(const float4*)&As[k][ty * 4];
            float4 b4 = *(const float4*)&Bs[k][tx * 4];
            float ar[4] = {a4.x, a4.y, a4.z, a4.w};
            float br[4] = {b4.x, b4.y, b4.z, b4.w};
            #pragma unroll
            for (int i = 0; i < 4; i++)
                #pragma unroll
                for (int j = 0; j < 4; j++)
                    acc[i][j] = fmaf(ar[i], br[j], acc[i][j]);
        }
        __syncthreads();
    }

    #pragma unroll
    for (int i = 0; i < 4; i++) {
        int m = m0 + ty * 4 + i;
        if (m >= M) continue;
        #pragma unroll
        for (int j = 0; j < 4; j++) {
            int n = n0 + tx * 4 + j;
            if (n >= N) continue;
            float v = acc[i][j];
            if (EPI == 1) v = geluf_(v + bias[n]);
            if (EPI == 2) v = v + bias[n] + resid[(size_t)m * N + n];
            C[(size_t)m * N + n] = v;
        }
    }
}

// ---------------- launch ----------------
extern "C" void kernel_launch(void* const* d_in, const int* in_sizes, int n_in,
                              void* d_out, int out_size)
{
    const float* x          = (const float*)d_in[0];
    const float* in_proj_w  = (const float*)d_in[1];
    const float* conv_w     = (const float*)d_in[2];
    const float* conv_b     = (const float*)d_in[3];
    const float* dt_bias    = (const float*)d_in[4];
    const float* A_log      = (const float*)d_in[5];
    const float* D_param    = (const float*)d_in[6];
    const float* norm_w     = (const float*)d_in[7];
    const float* out_proj_w = (const float*)d_in[8];
    const float* ln1_w      = (const float*)d_in[9];
    const float* ln1_b      = (const float*)d_in[10];
    const float* ln2_w      = (const float*)d_in[11];
    const float* ln2_b      = (const float*)d_in[12];
    const float* ff_w1      = (const float*)d_in[13];
    const float* ff_b1      = (const float*)d_in[14];
    const float* ff_w2      = (const float*)d_in[15];
    const float* ff_b2      = (const float*)d_in[16];
    float* out = (float*)d_out;

    float *p_xn, *p_zx, *p_dt, *p_dA, *p_conv, *p_y, *p_ysum, *p_mp, *p_m, *p_ff1;
    cudaGetSymbolAddress((void**)&p_xn,   g_xn);
    cudaGetSymbolAddress((void**)&p_zx,   g_zx);
    cudaGetSymbolAddress((void**)&p_dt,   g_dt);
    cudaGetSymbolAddress((void**)&p_dA,   g_dA);
    cudaGetSymbolAddress((void**)&p_conv, g_conv);
    cudaGetSymbolAddress((void**)&p_y,    g_y);
    cudaGetSymbolAddress((void**)&p_ysum, g_ysum);
    cudaGetSymbolAddress((void**)&p_mp,   g_mp);
    cudaGetSymbolAddress((void**)&p_m,    g_m);
    cudaGetSymbolAddress((void**)&p_ff1,  g_ff1);

    // 1) LN1
    ln_kernel<<<NTOK, 256>>>(x, ln1_w, ln1_b, p_xn);
    // 2) in_proj: [1024,3224] = xn @ Wᵀ  (shared by both directions)
    gemm_kernel<0><<<dim3((D_IN_PROJ + 63) / 64, NTOK / 64), 256>>>(
        p_xn, in_proj_w, nullptr, nullptr, p_zx, NTOK, D_IN_PROJ, D_MODEL);
    // 3) dt preprocessing
    dt_kernel<<<(NTOK * NHEADS + 255) / 256, 256>>>(p_zx, dt_bias, A_log, p_dt, p_dA);
    // 4) conv + silu (both directions)
    {
        long long total = 2LL * NTOK * CONV_DIM;
        conv_kernel<<<(unsigned)((total + 255) / 256), 256>>>(p_zx, conv_w, conv_b, p_conv);
    }
    // 5) SSM scan (both directions)
    scan_kernel<<<dim3(NHEADS, BSZ, 2), 64>>>(p_conv, p_dt, p_dA, D_param, p_y);
    // 6) gate + rmsnorm + combine directions
    gate_kernel<<<dim3(SEQ, BSZ), 256>>>(p_y, p_zx, norm_w, p_ysum);
    // 7) out_proj (single GEMM covers out_f + out_b)
    gemm_kernel<0><<<dim3(D_MODEL / 64, NTOK / 64), 256>>>(
        p_ysum, out_proj_w, nullptr, nullptr, p_mp, NTOK, D_MODEL, D_INNER);
    // 8) LN2
    ln_kernel<<<NTOK, 256>>>(p_mp, ln2_w, ln2_b, p_m);
    // 9) FFN1 (+bias, gelu)
    gemm_kernel<1><<<dim3(D_FF / 64, NTOK / 64), 256>>>(
        p_m, ff_w1, ff_b1, nullptr, p_ff1, NTOK, D_FF, D_MODEL);
    // 10) FFN2 (+bias, +residual x) -> d_out
    gemm_kernel<2><<<dim3(D_MODEL / 64, NTOK / 64), 256>>>(
        p_ff1, ff_w2, ff_b2, x, out, NTOK, D_MODEL, D_FF);
}